// round 12
// baseline (speedup 1.0000x reference)
#include <cuda_runtime.h>
#include <cuda_bf16.h>
#include <cstdint>
#include <math.h>

// Problem constants
#define NN 50000
#define EG 800000

// ---------------- scratch (device globals; no runtime allocation) ----------
__device__ float  g_Q   [(size_t)NN * 128];
__device__ float  g_K   [(size_t)NN * 128];
__device__ float  g_V   [(size_t)NN * 128];
__device__ float  g_h1  [(size_t)NN * 128];
__device__ float  g_wV  [(size_t)NN * 128];
__device__ float  g_z   [(size_t)NN * 8];
__device__ float  g_EA  [(size_t)EG * 128];
__device__ float  g_e1  [(size_t)EG * 128];
__device__ double g_sum [4 * 128];
__device__ double g_sq  [4 * 128];
__device__ float  g_bnsc[4 * 128];
__device__ float  g_bnsh[4 * 128];

// pre-split weights: hi plane [0, TOTW), lo plane [TOTW, 2*TOTW), bf16
#define OFF_WQ   0
#define OFF_WK   16384
#define OFF_WV   32768
#define OFF_WE   49152
#define OFF_WOH  65536
#define OFF_WOE  81920
#define OFF_WH1  98304
#define OFF_WE1  131072
#define OFF_WH2  163840
#define OFF_WE2  196608
#define TOTW     229376
__device__ __nv_bfloat16 g_Wb[2 * TOTW];

// ---------------- zero accumulators ----------------------------------------
__global__ void k_zero() {
    size_t i = (size_t)blockIdx.x * blockDim.x + threadIdx.x;
    size_t stride = (size_t)gridDim.x * blockDim.x;
    for (size_t j = i; j < (size_t)NN * 128; j += stride) g_wV[j] = 0.f;
    for (size_t j = i; j < (size_t)NN * 8;   j += stride) g_z[j]  = 0.f;
    if (i < 512) { g_sum[i] = 0.0; g_sq[i] = 0.0; }
}

// ============================================================================
// helpers
// ============================================================================
__device__ __forceinline__ uint32_t smem_u32(const void* p) {
    uint32_t a;
    asm("{ .reg .u64 t; cvta.to.shared.u64 t, %1; cvt.u32.u64 %0, t; }"
        : "=r"(a) : "l"(p));
    return a;
}

__device__ __forceinline__ void ldsm_x4(uint32_t addr, uint32_t* r) {
    asm volatile("ldmatrix.sync.aligned.m8n8.x4.shared.b16 {%0,%1,%2,%3}, [%4];"
        : "=r"(r[0]), "=r"(r[1]), "=r"(r[2]), "=r"(r[3]) : "r"(addr));
}

__device__ __forceinline__ void mma_bf16(float* acc, const uint32_t* a, const uint32_t* b) {
    asm volatile(
        "mma.sync.aligned.m16n8k16.row.col.f32.bf16.bf16.f32 "
        "{%0,%1,%2,%3},{%4,%5,%6,%7},{%8,%9},{%0,%1,%2,%3};"
        : "+f"(acc[0]), "+f"(acc[1]), "+f"(acc[2]), "+f"(acc[3])
        : "r"(a[0]), "r"(a[1]), "r"(a[2]), "r"(a[3]), "r"(b[0]), "r"(b[1]));
}

__device__ __forceinline__ void split_pair(float x0, float x1, uint32_t& hi, uint32_t& lo)
{
    __nv_bfloat162 h = __floats2bfloat162_rn(x0, x1);
    float r0 = x0 - __bfloat162float(__low2bfloat16(h));
    float r1 = x1 - __bfloat162float(__high2bfloat16(h));
    __nv_bfloat162 l = __floats2bfloat162_rn(r0, r1);
    hi = *reinterpret_cast<uint32_t*>(&h);
    lo = *reinterpret_cast<uint32_t*>(&l);
}

// ============================================================================
// Weight pre-split
// ============================================================================
__global__ __launch_bounds__(256)
void k_wsplit(const float* __restrict__ WQ,  const float* __restrict__ WK,
              const float* __restrict__ WV,  const float* __restrict__ WE,
              const float* __restrict__ WOh, const float* __restrict__ WOe,
              const float* __restrict__ Wh1, const float* __restrict__ We1,
              const float* __restrict__ Wh2, const float* __restrict__ We2)
{
    int p = blockIdx.x * 256 + threadIdx.x;
    if (p >= TOTW / 2) return;
    const float* W;
    int Kd, Nd, local, base;
    if (p < 49152) {
        int m = p >> 13;
        local = p & 8191;
        Kd = 128; Nd = 128; base = m << 14;
        W = (m == 0) ? WQ : (m == 1) ? WK : (m == 2) ? WV :
            (m == 3) ? WE : (m == 4) ? WOh : WOe;
    } else if (p < 65536)  { local = p - 49152; Kd = 128; Nd = 256; base = OFF_WH1; W = Wh1; }
    else if (p < 81920)    { local = p - 65536; Kd = 128; Nd = 256; base = OFF_WE1; W = We1; }
    else if (p < 98304)    { local = p - 81920; Kd = 256; Nd = 128; base = OFF_WH2; W = Wh2; }
    else                   { local = p - 98304; Kd = 256; Nd = 128; base = OFF_WE2; W = We2; }
    int n  = local % Nd;
    int k  = (local / Nd) * 2;
    float x0 = W[(size_t)k * Nd + n];
    float x1 = W[(size_t)(k + 1) * Nd + n];
    uint32_t hi, lo;
    split_pair(x0, x1, hi, lo);
    size_t o = (size_t)base + (size_t)n * Kd + k;
    *(uint32_t*)((char*)g_Wb + o * 2)          = hi;
    *(uint32_t*)((char*)g_Wb + (o + TOTW) * 2) = lo;
}

// ============================================================================
// Multi-problem pipelined HMMA bf16 3-split GEMM. K=128, N=128 per problem.
// Up to 4 problems in one launch; tiles ordered problem-major. B reloaded
// per CTA only when the grid-stride crosses a problem boundary.
// ============================================================================
#define A_CH_B 10240
#define A_BUF_B 20480
#define B_BASE 40960

struct P4 {
    const float* A[4];
    const __nv_bfloat16* Whi[4];
    const __nv_bfloat16* Wlo[4];
    const float* bias[4];
    const float* res[4];
    float* C[4];
    const float* Zrow[4];
    double* sumP[4];
    double* sqP[4];
    int tileEnd[4];
    int M[4];
    int nprob;
};

__device__ __forceinline__ int prob_of(const P4& p, int t) {
    int i = 0;
    while (i + 1 < p.nprob && t >= p.tileEnd[i]) i++;
    return i;
}

__device__ __forceinline__ void pf_chunk(const P4& p, int tn, int kc, int tid,
                                         float4* pf, int totTiles)
{
    if (tn >= totTiles) return;
    int pr = prob_of(p, tn);
    int tl = tn - (pr ? p.tileEnd[pr - 1] : 0);
    const float* A = p.A[pr];
    int M = p.M[pr];
    int m0 = tl << 7, kb = kc << 5;
    #pragma unroll
    for (int j = 0; j < 4; j++) {
        int idx = tid + (j << 8);
        int gm = m0 + (idx >> 3); if (gm > M - 1) gm = M - 1;
        pf[j] = *(const float4*)(A + (size_t)gm * 128 + kb + ((idx & 7) << 2));
    }
}

__global__ __launch_bounds__(256, 2)
void k_gemm_multi(P4 p, int totTiles)
{
    extern __shared__ char smem[];
    constexpr int BS = 136;
    constexpr uint32_t BBs = 128u * BS * 2u;
    const uint32_t sbase = smem_u32(smem);

    const int tid  = threadIdx.x;
    const int lane = tid & 31;
    const int wid  = tid >> 5;
    const int wm   = wid >> 2;
    const int wn   = wid & 3;
    const int a_row = (lane & 15);
    const int a_k   = (lane >> 4) << 3;
    const int b_row = (lane & 7) + ((lane >> 4) << 3);
    const int b_k   = ((lane >> 3) & 1) << 3;

    int curProb = -1;
    float4 pf[4];
    int t = blockIdx.x;
    if (t < totTiles) pf_chunk(p, t, 0, tid, pf, totTiles);
    int buf = 0;

    for (; t < totTiles; t += gridDim.x) {
        const int pr = prob_of(p, t);
        const int tl = t - (pr ? p.tileEnd[pr - 1] : 0);
        const int m0 = tl << 7;
        const int M  = p.M[pr];
        const float* Zrow = p.Zrow[pr];

        if (pr != curProb) {
            __syncthreads();   // all warps done with old B
            const __nv_bfloat16* Whi = p.Whi[pr];
            const __nv_bfloat16* Wlo = p.Wlo[pr];
            for (int i = tid; i < 128 * 16; i += 256) {
                int k8 = i & 15;
                int n  = i >> 4;
                uint4 vh = *(const uint4*)(Whi + (size_t)n * 128 + (k8 << 3));
                uint4 vl = *(const uint4*)(Wlo + (size_t)n * 128 + (k8 << 3));
                uint32_t off = ((uint32_t)n * BS + (k8 << 3)) * 2u;
                *(uint4*)(smem + B_BASE + off)       = vh;
                *(uint4*)(smem + B_BASE + BBs + off) = vl;
            }
            curProb = pr;
        }

        float acc[4][4][4] = {};
        for (int kc = 0; kc < 4; kc++) {
            const int kb = kc << 5;
            {
                char* ah_base = smem + buf * A_BUF_B;
                #pragma unroll
                for (int j = 0; j < 4; j++) {
                    int idx = tid + (j << 8);
                    int row = idx >> 3;
                    int c4  = (idx & 7) << 2;
                    float4 v = pf[j];
                    if (Zrow) {
                        int gm = m0 + row; if (gm > M - 1) gm = M - 1;
                        float zz = 1.0f / (Zrow[(size_t)gm * 8 + ((kb + c4) >> 4)] + 1e-6f);
                        v.x *= zz; v.y *= zz; v.z *= zz; v.w *= zz;
                    }
                    uint32_t h01, l01, h23, l23;
                    split_pair(v.x, v.y, h01, l01);
                    split_pair(v.z, v.w, h23, l23);
                    uint32_t off = ((uint32_t)row * 40 + c4) * 2u;
                    *(uint2*)(ah_base + off)          = make_uint2(h01, h23);
                    *(uint2*)(ah_base + A_CH_B + off) = make_uint2(l01, l23);
                }
            }
            __syncthreads();
            {
                int kc2 = kc + 1, tn = t;
                if (kc2 == 4) { kc2 = 0; tn = t + gridDim.x; }
                pf_chunk(p, tn, kc2, tid, pf, totTiles);
            }
            const uint32_t abase = sbase + buf * A_BUF_B;
            #pragma unroll
            for (int ks = 0; ks < 2; ks++) {
                const int ka = ks << 4;
                uint32_t bh[4][2], bl[4][2];
                #pragma unroll
                for (int np = 0; np < 2; np++) {
                    uint32_t roff = ((uint32_t)(wn * 32 + np * 16 + b_row) * BS
                                     + kb + ka + b_k) * 2u;
                    uint32_t rh[4], rl[4];
                    ldsm_x4(sbase + B_BASE + roff, rh);
                    ldsm_x4(sbase + B_BASE + BBs + roff, rl);
                    bh[np*2][0] = rh[0]; bh[np*2][1] = rh[1];
                    bh[np*2+1][0] = rh[2]; bh[np*2+1][1] = rh[3];
                    bl[np*2][0] = rl[0]; bl[np*2][1] = rl[1];
                    bl[np*2+1][0] = rl[2]; bl[np*2+1][1] = rl[3];
                }
                uint32_t ah[4][4], al[4][4];
                #pragma unroll
                for (int mt = 0; mt < 4; mt++) {
                    uint32_t roff = ((uint32_t)(wm * 64 + mt * 16 + a_row) * 40
                                     + ka + a_k) * 2u;
                    ldsm_x4(abase + roff, ah[mt]);
                    ldsm_x4(abase + A_CH_B + roff, al[mt]);
                }
                #pragma unroll
                for (int mt = 0; mt < 4; mt++)
                    #pragma unroll
                    for (int nt = 0; nt < 4; nt++) {
                        mma_bf16(acc[mt][nt], ah[mt], bh[nt]);
                        mma_bf16(acc[mt][nt], ah[mt], bl[nt]);
                        mma_bf16(acc[mt][nt], al[mt], bh[nt]);
                    }
            }
            buf ^= 1;
        }

        const int g  = lane >> 2;
        const int t2 = (lane & 3) << 1;
        const float* bias = p.bias[pr];
        const float* res  = p.res[pr];
        float* C          = p.C[pr];
        double* sumP      = p.sumP[pr];
        double* sqP       = p.sqP[pr];
        #pragma unroll
        for (int nt = 0; nt < 4; nt++) {
            int c0 = wn * 32 + nt * 8 + t2;
            float2 bv = *(const float2*)(bias + c0);
            float ps0 = 0.f, ps1 = 0.f, q0 = 0.f, q1 = 0.f;
            #pragma unroll
            for (int mt = 0; mt < 4; mt++) {
                #pragma unroll
                for (int half = 0; half < 2; half++) {
                    int r = m0 + wm * 64 + mt * 16 + g + half * 8;
                    float2 v = make_float2(acc[mt][nt][half*2]   + bv.x,
                                           acc[mt][nt][half*2+1] + bv.y);
                    if (r < M) {
                        size_t o = (size_t)r * 128 + c0;
                        if (res) {
                            float2 rv = *(const float2*)(res + o);
                            v.x += rv.x; v.y += rv.y;
                        }
                        *(float2*)(C + o) = v;
                    } else { v.x = 0.f; v.y = 0.f; }
                    ps0 += v.x; q0 += v.x * v.x;
                    ps1 += v.y; q1 += v.y * v.y;
                }
            }
            if (sumP) {
                #pragma unroll
                for (int off = 16; off >= 4; off >>= 1) {
                    ps0 += __shfl_down_sync(0xffffffffu, ps0, off);
                    ps1 += __shfl_down_sync(0xffffffffu, ps1, off);
                    q0  += __shfl_down_sync(0xffffffffu, q0,  off);
                    q1  += __shfl_down_sync(0xffffffffu, q1,  off);
                }
                if (lane < 4) {
                    int cc = wn * 32 + nt * 8 + lane * 2;
                    atomicAdd(&sumP[cc],     (double)ps0);
                    atomicAdd(&sumP[cc + 1], (double)ps1);
                    atomicAdd(&sqP[cc],      (double)q0);
                    atomicAdd(&sqP[cc + 1],  (double)q1);
                }
            }
        }
    }
}

// ============================================================================
// Generic smem-GEMM step (A rows 136, W rows 136, hi/lo splits)
// ============================================================================
__device__ __forceinline__ void ff_gemm(uint32_t sbase, uint32_t aHi, uint32_t aLo,
                                        uint32_t wHi, uint32_t wLo,
                                        int lane, int wm, int wn, float acc[4][4][4])
{
    const int a_row = (lane & 15);
    const int a_k   = (lane >> 4) << 3;
    const int b_row = (lane & 7) + ((lane >> 4) << 3);
    const int b_k   = ((lane >> 3) & 1) << 3;
    #pragma unroll
    for (int ks = 0; ks < 8; ks++) {
        const int ka = ks << 4;
        uint32_t bh[4][2], bl[4][2];
        #pragma unroll
        for (int np = 0; np < 2; np++) {
            uint32_t roff = ((uint32_t)(wn * 32 + np * 16 + b_row) * 136 + ka + b_k) * 2u;
            uint32_t rh[4], rl[4];
            ldsm_x4(sbase + wHi + roff, rh);
            ldsm_x4(sbase + wLo + roff, rl);
            bh[np*2][0] = rh[0]; bh[np*2][1] = rh[1];
            bh[np*2+1][0] = rh[2]; bh[np*2+1][1] = rh[3];
            bl[np*2][0] = rl[0]; bl[np*2][1] = rl[1];
            bl[np*2+1][0] = rl[2]; bl[np*2+1][1] = rl[3];
        }
        uint32_t ah[4][4], al[4][4];
        #pragma unroll
        for (int mt = 0; mt < 4; mt++) {
            uint32_t roff = ((uint32_t)(wm * 64 + mt * 16 + a_row) * 136 + ka + a_k) * 2u;
            ldsm_x4(sbase + aHi + roff, ah[mt]);
            ldsm_x4(sbase + aLo + roff, al[mt]);
        }
        #pragma unroll
        for (int mt = 0; mt < 4; mt++)
            #pragma unroll
            for (int nt = 0; nt < 4; nt++) {
                mma_bf16(acc[mt][nt], ah[mt], bh[nt]);
                mma_bf16(acc[mt][nt], ah[mt], bl[nt]);
                mma_bf16(acc[mt][nt], al[mt], bh[nt]);
            }
    }
}

// ============================================================================
// Merged fused FFN (h and e problems in one launch; weights streamed per tile)
// out = bn1(x) + relu(bn1(x)@W1 + b1)@W2 + b2, BN2 stats fused.
// ============================================================================
#define FF_A_HI 0
#define FF_A_LO 34816
#define FF_H_HI 69632
#define FF_H_LO 104448
#define FF_W_HI 139264
#define FF_W_LO 174080

struct F2 {
    const float* A[2];
    const __nv_bfloat16 *W1hi[2], *W1lo[2], *W2hi[2], *W2lo[2];
    const float *b1[2], *b2[2];
    float* C[2];
    const float *Asc[2], *Ash[2];
    double *sumP[2], *sqP[2];
    int tileEnd0;
    int M[2];
};

__global__ __launch_bounds__(256, 1)
void k_ffn_multi(F2 p, int totTiles)
{
    extern __shared__ char smem[];
    const uint32_t sbase = smem_u32(smem);
    const int tid  = threadIdx.x;
    const int lane = tid & 31;
    const int wid  = tid >> 5;
    const int wm   = wid >> 2;
    const int wn   = wid & 3;
    const int g    = lane >> 2;
    const int t2   = (lane & 3) << 1;

    for (int t = blockIdx.x; t < totTiles; t += gridDim.x) {
        const int pr = (t >= p.tileEnd0) ? 1 : 0;
        const int tl = pr ? (t - p.tileEnd0) : t;
        const int m0 = tl << 7;
        const int M  = p.M[pr];
        const float* A   = p.A[pr];
        const float* Asc = p.Asc[pr];
        const float* Ash = p.Ash[pr];
        __syncthreads();

        for (int j = 0; j < 16; j++) {
            int idx = tid + (j << 8);
            int row = idx >> 5;
            int c4  = (idx & 31) << 2;
            int gm = m0 + row; if (gm > M - 1) gm = M - 1;
            float4 v = *(const float4*)(A + (size_t)gm * 128 + c4);
            float4 sc = *(const float4*)(Asc + c4);
            float4 sh = *(const float4*)(Ash + c4);
            v.x = v.x * sc.x + sh.x;
            v.y = v.y * sc.y + sh.y;
            v.z = v.z * sc.z + sh.z;
            v.w = v.w * sc.w + sh.w;
            uint32_t h01, l01, h23, l23;
            split_pair(v.x, v.y, h01, l01);
            split_pair(v.z, v.w, h23, l23);
            uint32_t off = ((uint32_t)row * 136 + c4) * 2u;
            *(uint2*)(smem + FF_A_HI + off) = make_uint2(h01, h23);
            *(uint2*)(smem + FF_A_LO + off) = make_uint2(l01, l23);
        }
        {
            const __nv_bfloat16* W1hi = p.W1hi[pr];
            const __nv_bfloat16* W1lo = p.W1lo[pr];
            for (int i = tid; i < 2048; i += 256) {
                int n = i >> 4, k8 = i & 15;
                uint4 vh = *(const uint4*)(W1hi + (size_t)n * 128 + (k8 << 3));
                uint4 vl = *(const uint4*)(W1lo + (size_t)n * 128 + (k8 << 3));
                uint32_t off = ((uint32_t)n * 136 + (k8 << 3)) * 2u;
                *(uint4*)(smem + FF_W_HI + off) = vh;
                *(uint4*)(smem + FF_W_LO + off) = vl;
            }
        }
        __syncthreads();

        float acc2[4][4][4] = {};
        #pragma unroll
        for (int nh = 0; nh < 2; nh++) {
            float acc1[4][4][4] = {};
            ff_gemm(sbase, FF_A_HI, FF_A_LO, FF_W_HI, FF_W_LO, lane, wm, wn, acc1);
            __syncthreads();
            #pragma unroll
            for (int mt = 0; mt < 4; mt++) {
                #pragma unroll
                for (int nt = 0; nt < 4; nt++) {
                    int c = wn * 32 + nt * 8 + t2;
                    float2 bv = *(const float2*)(p.b1[pr] + nh * 128 + c);
                    #pragma unroll
                    for (int half = 0; half < 2; half++) {
                        int rloc = wm * 64 + mt * 16 + g + half * 8;
                        float v0 = fmaxf(acc1[mt][nt][half*2]   + bv.x, 0.f);
                        float v1 = fmaxf(acc1[mt][nt][half*2+1] + bv.y, 0.f);
                        uint32_t hi, lo;
                        split_pair(v0, v1, hi, lo);
                        uint32_t off = ((uint32_t)rloc * 136 + c) * 2u;
                        *(uint32_t*)(smem + FF_H_HI + off) = hi;
                        *(uint32_t*)(smem + FF_H_LO + off) = lo;
                    }
                }
            }
            {
                const __nv_bfloat16* W2hi = p.W2hi[pr];
                const __nv_bfloat16* W2lo = p.W2lo[pr];
                for (int i = tid; i < 2048; i += 256) {
                    int n = i >> 4, k8 = i & 15;
                    uint4 vh = *(const uint4*)(W2hi + (size_t)n * 256 + nh * 128 + (k8 << 3));
                    uint4 vl = *(const uint4*)(W2lo + (size_t)n * 256 + nh * 128 + (k8 << 3));
                    uint32_t off = ((uint32_t)n * 136 + (k8 << 3)) * 2u;
                    *(uint4*)(smem + FF_W_HI + off) = vh;
                    *(uint4*)(smem + FF_W_LO + off) = vl;
                }
            }
            __syncthreads();
            ff_gemm(sbase, FF_H_HI, FF_H_LO, FF_W_HI, FF_W_LO, lane, wm, wn, acc2);
            if (nh == 0) {
                __syncthreads();
                const __nv_bfloat16* W1hi = p.W1hi[pr];
                const __nv_bfloat16* W1lo = p.W1lo[pr];
                for (int i = tid; i < 2048; i += 256) {
                    int n = i >> 4, k8 = i & 15;
                    uint4 vh = *(const uint4*)(W1hi + (size_t)(128 + n) * 128 + (k8 << 3));
                    uint4 vl = *(const uint4*)(W1lo + (size_t)(128 + n) * 128 + (k8 << 3));
                    uint32_t off = ((uint32_t)n * 136 + (k8 << 3)) * 2u;
                    *(uint4*)(smem + FF_W_HI + off) = vh;
                    *(uint4*)(smem + FF_W_LO + off) = vl;
                }
                __syncthreads();
            }
        }

        float* C = p.C[pr];
        #pragma unroll
        for (int nt = 0; nt < 4; nt++) {
            int c0 = wn * 32 + nt * 8 + t2;
            float2 bv = *(const float2*)(p.b2[pr] + c0);
            float ps0 = 0.f, ps1 = 0.f, q0 = 0.f, q1 = 0.f;
            #pragma unroll
            for (int mt = 0; mt < 4; mt++) {
                #pragma unroll
                for (int half = 0; half < 2; half++) {
                    int rloc = wm * 64 + mt * 16 + g + half * 8;
                    int r = m0 + rloc;
                    uint32_t off = ((uint32_t)rloc * 136 + c0) * 2u;
                    __nv_bfloat162 rh = *(__nv_bfloat162*)(smem + FF_A_HI + off);
                    __nv_bfloat162 rl = *(__nv_bfloat162*)(smem + FF_A_LO + off);
                    float2 v;
                    v.x = acc2[mt][nt][half*2]   + bv.x
                        + __bfloat162float(__low2bfloat16(rh))
                        + __bfloat162float(__low2bfloat16(rl));
                    v.y = acc2[mt][nt][half*2+1] + bv.y
                        + __bfloat162float(__high2bfloat16(rh))
                        + __bfloat162float(__high2bfloat16(rl));
                    if (r < M) {
                        *(float2*)(C + (size_t)r * 128 + c0) = v;
                    } else { v.x = 0.f; v.y = 0.f; }
                    ps0 += v.x; q0 += v.x * v.x;
                    ps1 += v.y; q1 += v.y * v.y;
                }
            }
            #pragma unroll
            for (int off = 16; off >= 4; off >>= 1) {
                ps0 += __shfl_down_sync(0xffffffffu, ps0, off);
                ps1 += __shfl_down_sync(0xffffffffu, ps1, off);
                q0  += __shfl_down_sync(0xffffffffu, q0,  off);
                q1  += __shfl_down_sync(0xffffffffu, q1,  off);
            }
            if (lane < 4) {
                int cc = wn * 32 + nt * 8 + lane * 2;
                atomicAdd(&p.sumP[pr][cc],     (double)ps0);
                atomicAdd(&p.sumP[pr][cc + 1], (double)ps1);
                atomicAdd(&p.sqP[pr][cc],      (double)q0);
                atomicAdd(&p.sqP[pr][cc + 1],  (double)q1);
            }
        }
    }
}

// ---------------- edge kernel: 1 warp = 4 edges, float4 vector atomics ------
__global__ __launch_bounds__(256)
void k_edge(const int* __restrict__ src, const int* __restrict__ dst)
{
    const int lane = threadIdx.x & 31;
    const int e0 = (blockIdx.x * 8 + (threadIdx.x >> 5)) * 4;
    const int c4 = lane << 2;
    int s[4], d[4];
    #pragma unroll
    for (int i = 0; i < 4; i++) { s[i] = src[e0 + i]; d[i] = dst[e0 + i]; }
    float4 kv[4], qv[4], ev[4], vv[4];
    #pragma unroll
    for (int i = 0; i < 4; i++) {
        kv[i] = *(const float4*)(g_K + (size_t)s[i] * 128 + c4);
        qv[i] = *(const float4*)(g_Q + (size_t)d[i] * 128 + c4);
        ev[i] = *(const float4*)(g_EA + (size_t)(e0 + i) * 128 + c4);
        vv[i] = *(const float4*)(g_V + (size_t)s[i] * 128 + c4);
    }
    #pragma unroll
    for (int i = 0; i < 4; i++) {
        float4 sc;
        sc.x = kv[i].x * qv[i].x * 0.25f * ev[i].x;
        sc.y = kv[i].y * qv[i].y * 0.25f * ev[i].y;
        sc.z = kv[i].z * qv[i].z * 0.25f * ev[i].z;
        sc.w = kv[i].w * qv[i].w * 0.25f * ev[i].w;
        *(float4*)(g_EA + (size_t)(e0 + i) * 128 + c4) = sc;
        float sum = sc.x + sc.y + sc.z + sc.w;
        sum += __shfl_xor_sync(0xffffffffu, sum, 1);
        sum += __shfl_xor_sync(0xffffffffu, sum, 2);
        sum = fminf(fmaxf(sum, -5.f), 5.f);
        float ss = __expf(sum);
        float4 add = make_float4(vv[i].x * ss, vv[i].y * ss, vv[i].z * ss, vv[i].w * ss);
        atomicAdd((float4*)(g_wV + (size_t)d[i] * 128 + c4), add);
        if ((lane & 3) == 0)
            atomicAdd(&g_z[(size_t)d[i] * 8 + (lane >> 2)], ss);
    }
}

// ---------------- batch-norm finalize (2 slots) / merged apply --------------
__global__ void k_bn_fin2(int slotA, float MfA, const float* gA, const float* bA,
                          int slotB, float MfB, const float* gB, const float* bB)
{
    int c = threadIdx.x & 127;
    int slot; float Mf; const float *gg, *bb;
    if (threadIdx.x < 128) { slot = slotA; Mf = MfA; gg = gA; bb = bA; }
    else                   { slot = slotB; Mf = MfB; gg = gB; bb = bB; }
    double mu  = g_sum[slot * 128 + c] / (double)Mf;
    double var = g_sq [slot * 128 + c] / (double)Mf - mu * mu;
    float sc = gg[c] * rsqrtf((float)var + 1e-5f);
    g_bnsc[slot * 128 + c] = sc;
    g_bnsh[slot * 128 + c] = bb[c] - (float)mu * sc;
}

__global__ __launch_bounds__(256)
void k_bn_apply2(float* __restrict__ Xh, float* __restrict__ Xe)
{
    const size_t totH = (size_t)NN * 32;
    const size_t tot  = totH + (size_t)EG * 32;
    size_t i = (size_t)blockIdx.x * blockDim.x + threadIdx.x;
    size_t stride = (size_t)gridDim.x * blockDim.x;
    for (size_t j = i; j < tot; j += stride) {
        bool isH = j < totH;
        float* X = isH ? Xh : Xe;
        size_t jj = isH ? j : j - totH;
        int slot = isH ? 2 : 3;
        int c = (int)(jj & 31) * 4;
        const float* sc = g_bnsc + slot * 128 + c;
        const float* sh = g_bnsh + slot * 128 + c;
        float4 v = ((float4*)X)[jj];
        v.x = v.x * sc[0] + sh[0];
        v.y = v.y * sc[1] + sh[1];
        v.z = v.z * sc[2] + sh[2];
        v.w = v.w * sc[3] + sh[3];
        ((float4*)X)[jj] = v;
    }
}

// ---------------- host orchestration ---------------------------------------
extern "C" void kernel_launch(void* const* d_in, const int* in_sizes, int n_in,
                              void* d_out, int out_size)
{
    const float* h   = (const float*)d_in[0];
    const float* e   = (const float*)d_in[1];
    const int*   src = (const int*)d_in[2];
    const int*   dst = (const int*)d_in[3];
    const float* WQ  = (const float*)d_in[4];   const float* bQ  = (const float*)d_in[5];
    const float* WK  = (const float*)d_in[6];   const float* bK  = (const float*)d_in[7];
    const float* WV  = (const float*)d_in[8];   const float* bV  = (const float*)d_in[9];
    const float* WE  = (const float*)d_in[10];  const float* bE  = (const float*)d_in[11];
    const float* WOh = (const float*)d_in[12];  const float* bOh = (const float*)d_in[13];
    const float* WOe = (const float*)d_in[14];  const float* bOe = (const float*)d_in[15];
    const float* Wh1 = (const float*)d_in[16];  const float* bh1 = (const float*)d_in[17];
    const float* Wh2 = (const float*)d_in[18];  const float* bh2 = (const float*)d_in[19];
    const float* We1 = (const float*)d_in[20];  const float* be1 = (const float*)d_in[21];
    const float* We2 = (const float*)d_in[22];  const float* be2 = (const float*)d_in[23];
    const float* g1h = (const float*)d_in[24];
    const float* g1e = (const float*)d_in[25];
    const float* g2h = (const float*)d_in[26];
    const float* g2e = (const float*)d_in[27];
    const float* b1h = (const float*)d_in[28];
    const float* b1e = (const float*)d_in[29];
    const float* b2h = (const float*)d_in[30];
    const float* b2e = (const float*)d_in[31];

    float *pQ, *pK, *pV, *ph1, *pEA, *pe1, *pbnsc, *pbnsh, *pwV, *pz;
    double *psum, *psq;
    __nv_bfloat16* wb;
    cudaGetSymbolAddress((void**)&pQ,    g_Q);
    cudaGetSymbolAddress((void**)&pK,    g_K);
    cudaGetSymbolAddress((void**)&pV,    g_V);
    cudaGetSymbolAddress((void**)&ph1,   g_h1);
    cudaGetSymbolAddress((void**)&pEA,   g_EA);
    cudaGetSymbolAddress((void**)&pe1,   g_e1);
    cudaGetSymbolAddress((void**)&pbnsc, g_bnsc);
    cudaGetSymbolAddress((void**)&pbnsh, g_bnsh);
    cudaGetSymbolAddress((void**)&pwV,   g_wV);
    cudaGetSymbolAddress((void**)&pz,    g_z);
    cudaGetSymbolAddress((void**)&psum,  g_sum);
    cudaGetSymbolAddress((void**)&psq,   g_sq);
    cudaGetSymbolAddress((void**)&wb,    g_Wb);

    cudaFuncSetAttribute(k_gemm_multi, cudaFuncAttributeMaxDynamicSharedMemorySize, 110592);
    cudaFuncSetAttribute(k_ffn_multi,  cudaFuncAttributeMaxDynamicSharedMemorySize, 208896);

    float* out_h = (float*)d_out;
    float* out_e = (float*)d_out + (size_t)NN * 128;

    const int tilesH = (NN + 127) / 128;   // 391
    const int tilesE = (EG + 127) / 128;   // 6250

    // 0) zero + weight pre-split
    k_zero<<<4096, 256>>>();
    k_wsplit<<<448, 256>>>(WQ, WK, WV, WE, WOh, WOe, Wh1, We1, Wh2, We2);

    // 1) all four projections in one launch: Q, K, V (A=h), E (A=e)
    {
        P4 p = {};
        p.nprob = 4;
        p.A[0] = h;  p.A[1] = h;  p.A[2] = h;  p.A[3] = e;
        p.Whi[0] = wb + OFF_WQ; p.Wlo[0] = wb + OFF_WQ + TOTW;
        p.Whi[1] = wb + OFF_WK; p.Wlo[1] = wb + OFF_WK + TOTW;
        p.Whi[2] = wb + OFF_WV; p.Wlo[2] = wb + OFF_WV + TOTW;
        p.Whi[3] = wb + OFF_WE; p.Wlo[3] = wb + OFF_WE + TOTW;
        p.bias[0] = bQ; p.bias[1] = bK; p.bias[2] = bV; p.bias[3] = bE;
        p.C[0] = pQ; p.C[1] = pK; p.C[2] = pV; p.C[3] = pEA;
        p.M[0] = NN; p.M[1] = NN; p.M[2] = NN; p.M[3] = EG;
        p.tileEnd[0] = tilesH;
        p.tileEnd[1] = tilesH * 2;
        p.tileEnd[2] = tilesH * 3;
        p.tileEnd[3] = tilesH * 3 + tilesE;
        int tot = p.tileEnd[3];
        int grid = tot < 296 ? tot : 296;
        k_gemm_multi<<<grid, 256, 110592>>>(p, tot);
    }

    // 2) edge scores + attention weights + segment sums
    k_edge<<<EG / 32, 256>>>(src, dst);

    // 3) O projections (Oh with Zrow + BN1h stats, Oe + BN1e stats) merged
    {
        P4 p = {};
        p.nprob = 2;
        p.A[0] = pwV; p.A[1] = pEA;
        p.Whi[0] = wb + OFF_WOH; p.Wlo[0] = wb + OFF_WOH + TOTW;
        p.Whi[1] = wb + OFF_WOE; p.Wlo[1] = wb + OFF_WOE + TOTW;
        p.bias[0] = bOh; p.bias[1] = bOe;
        p.res[0] = h;  p.res[1] = e;
        p.C[0] = ph1;  p.C[1] = pe1;
        p.Zrow[0] = pz;
        p.sumP[0] = psum + 0;   p.sqP[0] = psq + 0;
        p.sumP[1] = psum + 128; p.sqP[1] = psq + 128;
        p.M[0] = NN; p.M[1] = EG;
        p.tileEnd[0] = tilesH;
        p.tileEnd[1] = tilesH + tilesE;
        int tot = p.tileEnd[1];
        int grid = tot < 296 ? tot : 296;
        k_gemm_multi<<<grid, 256, 110592>>>(p, tot);
    }

    // 4) BN #1 finalize (both slots, one launch)
    k_bn_fin2<<<1, 256>>>(0, (float)NN, g1h, b1h, 1, (float)EG, g1e, b1e);

    // 5) fused FFNs, h + e merged
    {
        F2 p = {};
        p.A[0] = ph1; p.A[1] = pe1;
        p.W1hi[0] = wb + OFF_WH1; p.W1lo[0] = wb + OFF_WH1 + TOTW;
        p.W1hi[1] = wb + OFF_WE1; p.W1lo[1] = wb + OFF_WE1 + TOTW;
        p.W2hi[0] = wb + OFF_WH2; p.W2lo[0] = wb + OFF_WH2 + TOTW;
        p.W2hi[1] = wb + OFF_WE2; p.W2lo[1] = wb + OFF_WE2 + TOTW;
        p.b1[0] = bh1; p.b1[1] = be1;
        p.b2[0] = bh2; p.b2[1] = be2;
        p.C[0] = out_h; p.C[1] = out_e;
        p.Asc[0] = pbnsc + 0;   p.Ash[0] = pbnsh + 0;
        p.Asc[1] = pbnsc + 128; p.Ash[1] = pbnsh + 128;
        p.sumP[0] = psum + 256; p.sqP[0] = psq + 256;
        p.sumP[1] = psum + 384; p.sqP[1] = psq + 384;
        p.tileEnd0 = tilesH;
        p.M[0] = NN; p.M[1] = EG;
        int tot = tilesH + tilesE;
        int grid = tot < 148 ? tot : 148;
        k_ffn_multi<<<grid, 256, 208896>>>(p, tot);
    }

    // 6) BN #2 finalize + merged apply
    k_bn_fin2<<<1, 256>>>(2, (float)NN, g2h, b2h, 3, (float)EG, g2e, b2e);
    k_bn_apply2<<<8192, 256>>>(out_h, out_e);
}

// round 13
// speedup vs baseline: 1.0610x; 1.0610x over previous
#include <cuda_runtime.h>
#include <cuda_bf16.h>
#include <cstdint>
#include <math.h>

// Problem constants
#define NN 50000
#define EG 800000

// ---------------- scratch (device globals; no runtime allocation) ----------
__device__ float  g_Q   [(size_t)NN * 128];
__device__ float  g_K   [(size_t)NN * 128];
__device__ float  g_V   [(size_t)NN * 128];
__device__ float  g_h1  [(size_t)NN * 128];
__device__ float  g_wV  [(size_t)NN * 128];
__device__ float  g_z   [(size_t)NN * 8];
__device__ float  g_EA  [(size_t)EG * 128];
__device__ float  g_e1  [(size_t)EG * 128];
__device__ double g_sum [4 * 128];
__device__ double g_sq  [4 * 128];
__device__ float  g_bnsc[4 * 128];
__device__ float  g_bnsh[4 * 128];

// pre-split weights: hi plane [0, TOTW), lo plane [TOTW, 2*TOTW), bf16
#define OFF_WQ   0
#define OFF_WK   16384
#define OFF_WV   32768
#define OFF_WE   49152
#define OFF_WOH  65536
#define OFF_WOE  81920
#define OFF_WH1  98304
#define OFF_WE1  131072
#define OFF_WH2  163840
#define OFF_WE2  196608
#define TOTW     229376
__device__ __nv_bfloat16 g_Wb[2 * TOTW];

// ---------------- zero accumulators ----------------------------------------
__global__ void k_zero() {
    size_t i = (size_t)blockIdx.x * blockDim.x + threadIdx.x;
    size_t stride = (size_t)gridDim.x * blockDim.x;
    for (size_t j = i; j < (size_t)NN * 128; j += stride) g_wV[j] = 0.f;
    for (size_t j = i; j < (size_t)NN * 8;   j += stride) g_z[j]  = 0.f;
    if (i < 512) { g_sum[i] = 0.0; g_sq[i] = 0.0; }
}

// ============================================================================
// helpers
// ============================================================================
__device__ __forceinline__ uint32_t smem_u32(const void* p) {
    uint32_t a;
    asm("{ .reg .u64 t; cvta.to.shared.u64 t, %1; cvt.u32.u64 %0, t; }"
        : "=r"(a) : "l"(p));
    return a;
}

__device__ __forceinline__ void ldsm_x4(uint32_t addr, uint32_t* r) {
    asm volatile("ldmatrix.sync.aligned.m8n8.x4.shared.b16 {%0,%1,%2,%3}, [%4];"
        : "=r"(r[0]), "=r"(r[1]), "=r"(r[2]), "=r"(r[3]) : "r"(addr));
}

__device__ __forceinline__ void mma_bf16(float* acc, const uint32_t* a, const uint32_t* b) {
    asm volatile(
        "mma.sync.aligned.m16n8k16.row.col.f32.bf16.bf16.f32 "
        "{%0,%1,%2,%3},{%4,%5,%6,%7},{%8,%9},{%0,%1,%2,%3};"
        : "+f"(acc[0]), "+f"(acc[1]), "+f"(acc[2]), "+f"(acc[3])
        : "r"(a[0]), "r"(a[1]), "r"(a[2]), "r"(a[3]), "r"(b[0]), "r"(b[1]));
}

__device__ __forceinline__ void split_pair(float x0, float x1, uint32_t& hi, uint32_t& lo)
{
    __nv_bfloat162 h = __floats2bfloat162_rn(x0, x1);
    float r0 = x0 - __bfloat162float(__low2bfloat16(h));
    float r1 = x1 - __bfloat162float(__high2bfloat16(h));
    __nv_bfloat162 l = __floats2bfloat162_rn(r0, r1);
    hi = *reinterpret_cast<uint32_t*>(&h);
    lo = *reinterpret_cast<uint32_t*>(&l);
}

// ============================================================================
// Weight pre-split
// ============================================================================
__global__ __launch_bounds__(256)
void k_wsplit(const float* __restrict__ WQ,  const float* __restrict__ WK,
              const float* __restrict__ WV,  const float* __restrict__ WE,
              const float* __restrict__ WOh, const float* __restrict__ WOe,
              const float* __restrict__ Wh1, const float* __restrict__ We1,
              const float* __restrict__ Wh2, const float* __restrict__ We2)
{
    int p = blockIdx.x * 256 + threadIdx.x;
    if (p >= TOTW / 2) return;
    const float* W;
    int Kd, Nd, local, base;
    if (p < 49152) {
        int m = p >> 13;
        local = p & 8191;
        Kd = 128; Nd = 128; base = m << 14;
        W = (m == 0) ? WQ : (m == 1) ? WK : (m == 2) ? WV :
            (m == 3) ? WE : (m == 4) ? WOh : WOe;
    } else if (p < 65536)  { local = p - 49152; Kd = 128; Nd = 256; base = OFF_WH1; W = Wh1; }
    else if (p < 81920)    { local = p - 65536; Kd = 128; Nd = 256; base = OFF_WE1; W = We1; }
    else if (p < 98304)    { local = p - 81920; Kd = 256; Nd = 128; base = OFF_WH2; W = Wh2; }
    else                   { local = p - 98304; Kd = 256; Nd = 128; base = OFF_WE2; W = We2; }
    int n  = local % Nd;
    int k  = (local / Nd) * 2;
    float x0 = W[(size_t)k * Nd + n];
    float x1 = W[(size_t)(k + 1) * Nd + n];
    uint32_t hi, lo;
    split_pair(x0, x1, hi, lo);
    size_t o = (size_t)base + (size_t)n * Kd + k;
    *(uint32_t*)((char*)g_Wb + o * 2)          = hi;
    *(uint32_t*)((char*)g_Wb + (o + TOTW) * 2) = lo;
}

// ============================================================================
// Multi-problem pipelined HMMA bf16 3-split GEMM. K=128, N=128 per problem.
// ============================================================================
#define A_CH_B 10240
#define A_BUF_B 20480
#define B_BASE 40960

struct P4 {
    const float* A[4];
    const __nv_bfloat16* Whi[4];
    const __nv_bfloat16* Wlo[4];
    const float* bias[4];
    const float* res[4];
    float* C[4];
    const float* Zrow[4];
    double* sumP[4];
    double* sqP[4];
    int tileEnd[4];
    int M[4];
    int nprob;
};

__device__ __forceinline__ int prob_of(const P4& p, int t) {
    int i = 0;
    while (i + 1 < p.nprob && t >= p.tileEnd[i]) i++;
    return i;
}

__device__ __forceinline__ void pf_chunk(const P4& p, int tn, int kc, int tid,
                                         float4* pf, int totTiles)
{
    if (tn >= totTiles) return;
    int pr = prob_of(p, tn);
    int tl = tn - (pr ? p.tileEnd[pr - 1] : 0);
    const float* A = p.A[pr];
    int M = p.M[pr];
    int m0 = tl << 7, kb = kc << 5;
    #pragma unroll
    for (int j = 0; j < 4; j++) {
        int idx = tid + (j << 8);
        int gm = m0 + (idx >> 3); if (gm > M - 1) gm = M - 1;
        pf[j] = *(const float4*)(A + (size_t)gm * 128 + kb + ((idx & 7) << 2));
    }
}

__global__ __launch_bounds__(256, 2)
void k_gemm_multi(P4 p, int totTiles)
{
    extern __shared__ char smem[];
    constexpr int BS = 136;
    constexpr uint32_t BBs = 128u * BS * 2u;
    const uint32_t sbase = smem_u32(smem);

    const int tid  = threadIdx.x;
    const int lane = tid & 31;
    const int wid  = tid >> 5;
    const int wm   = wid >> 2;
    const int wn   = wid & 3;
    const int a_row = (lane & 15);
    const int a_k   = (lane >> 4) << 3;
    const int b_row = (lane & 7) + ((lane >> 4) << 3);
    const int b_k   = ((lane >> 3) & 1) << 3;

    int curProb = -1;
    float4 pf[4];
    int t = blockIdx.x;
    if (t < totTiles) pf_chunk(p, t, 0, tid, pf, totTiles);
    int buf = 0;

    for (; t < totTiles; t += gridDim.x) {
        const int pr = prob_of(p, t);
        const int tl = t - (pr ? p.tileEnd[pr - 1] : 0);
        const int m0 = tl << 7;
        const int M  = p.M[pr];
        const float* Zrow = p.Zrow[pr];

        if (pr != curProb) {
            __syncthreads();
            const __nv_bfloat16* Whi = p.Whi[pr];
            const __nv_bfloat16* Wlo = p.Wlo[pr];
            for (int i = tid; i < 128 * 16; i += 256) {
                int k8 = i & 15;
                int n  = i >> 4;
                uint4 vh = *(const uint4*)(Whi + (size_t)n * 128 + (k8 << 3));
                uint4 vl = *(const uint4*)(Wlo + (size_t)n * 128 + (k8 << 3));
                uint32_t off = ((uint32_t)n * BS + (k8 << 3)) * 2u;
                *(uint4*)(smem + B_BASE + off)       = vh;
                *(uint4*)(smem + B_BASE + BBs + off) = vl;
            }
            curProb = pr;
        }

        float acc[4][4][4] = {};
        for (int kc = 0; kc < 4; kc++) {
            const int kb = kc << 5;
            {
                char* ah_base = smem + buf * A_BUF_B;
                #pragma unroll
                for (int j = 0; j < 4; j++) {
                    int idx = tid + (j << 8);
                    int row = idx >> 3;
                    int c4  = (idx & 7) << 2;
                    float4 v = pf[j];
                    if (Zrow) {
                        int gm = m0 + row; if (gm > M - 1) gm = M - 1;
                        float zz = 1.0f / (Zrow[(size_t)gm * 8 + ((kb + c4) >> 4)] + 1e-6f);
                        v.x *= zz; v.y *= zz; v.z *= zz; v.w *= zz;
                    }
                    uint32_t h01, l01, h23, l23;
                    split_pair(v.x, v.y, h01, l01);
                    split_pair(v.z, v.w, h23, l23);
                    uint32_t off = ((uint32_t)row * 40 + c4) * 2u;
                    *(uint2*)(ah_base + off)          = make_uint2(h01, h23);
                    *(uint2*)(ah_base + A_CH_B + off) = make_uint2(l01, l23);
                }
            }
            __syncthreads();
            {
                int kc2 = kc + 1, tn = t;
                if (kc2 == 4) { kc2 = 0; tn = t + gridDim.x; }
                pf_chunk(p, tn, kc2, tid, pf, totTiles);
            }
            const uint32_t abase = sbase + buf * A_BUF_B;
            #pragma unroll
            for (int ks = 0; ks < 2; ks++) {
                const int ka = ks << 4;
                uint32_t bh[4][2], bl[4][2];
                #pragma unroll
                for (int np = 0; np < 2; np++) {
                    uint32_t roff = ((uint32_t)(wn * 32 + np * 16 + b_row) * BS
                                     + kb + ka + b_k) * 2u;
                    uint32_t rh[4], rl[4];
                    ldsm_x4(sbase + B_BASE + roff, rh);
                    ldsm_x4(sbase + B_BASE + BBs + roff, rl);
                    bh[np*2][0] = rh[0]; bh[np*2][1] = rh[1];
                    bh[np*2+1][0] = rh[2]; bh[np*2+1][1] = rh[3];
                    bl[np*2][0] = rl[0]; bl[np*2][1] = rl[1];
                    bl[np*2+1][0] = rl[2]; bl[np*2+1][1] = rl[3];
                }
                uint32_t ah[4][4], al[4][4];
                #pragma unroll
                for (int mt = 0; mt < 4; mt++) {
                    uint32_t roff = ((uint32_t)(wm * 64 + mt * 16 + a_row) * 40
                                     + ka + a_k) * 2u;
                    ldsm_x4(abase + roff, ah[mt]);
                    ldsm_x4(abase + A_CH_B + roff, al[mt]);
                }
                #pragma unroll
                for (int mt = 0; mt < 4; mt++)
                    #pragma unroll
                    for (int nt = 0; nt < 4; nt++) {
                        mma_bf16(acc[mt][nt], ah[mt], bh[nt]);
                        mma_bf16(acc[mt][nt], ah[mt], bl[nt]);
                        mma_bf16(acc[mt][nt], al[mt], bh[nt]);
                    }
            }
            buf ^= 1;
        }

        const int g  = lane >> 2;
        const int t2 = (lane & 3) << 1;
        const float* bias = p.bias[pr];
        const float* res  = p.res[pr];
        float* C          = p.C[pr];
        double* sumP      = p.sumP[pr];
        double* sqP       = p.sqP[pr];
        #pragma unroll
        for (int nt = 0; nt < 4; nt++) {
            int c0 = wn * 32 + nt * 8 + t2;
            float2 bv = *(const float2*)(bias + c0);
            float ps0 = 0.f, ps1 = 0.f, q0 = 0.f, q1 = 0.f;
            #pragma unroll
            for (int mt = 0; mt < 4; mt++) {
                #pragma unroll
                for (int half = 0; half < 2; half++) {
                    int r = m0 + wm * 64 + mt * 16 + g + half * 8;
                    float2 v = make_float2(acc[mt][nt][half*2]   + bv.x,
                                           acc[mt][nt][half*2+1] + bv.y);
                    if (r < M) {
                        size_t o = (size_t)r * 128 + c0;
                        if (res) {
                            float2 rv = *(const float2*)(res + o);
                            v.x += rv.x; v.y += rv.y;
                        }
                        *(float2*)(C + o) = v;
                    } else { v.x = 0.f; v.y = 0.f; }
                    ps0 += v.x; q0 += v.x * v.x;
                    ps1 += v.y; q1 += v.y * v.y;
                }
            }
            if (sumP) {
                #pragma unroll
                for (int off = 16; off >= 4; off >>= 1) {
                    ps0 += __shfl_down_sync(0xffffffffu, ps0, off);
                    ps1 += __shfl_down_sync(0xffffffffu, ps1, off);
                    q0  += __shfl_down_sync(0xffffffffu, q0,  off);
                    q1  += __shfl_down_sync(0xffffffffu, q1,  off);
                }
                if (lane < 4) {
                    int cc = wn * 32 + nt * 8 + lane * 2;
                    atomicAdd(&sumP[cc],     (double)ps0);
                    atomicAdd(&sumP[cc + 1], (double)ps1);
                    atomicAdd(&sqP[cc],      (double)q0);
                    atomicAdd(&sqP[cc + 1],  (double)q1);
                }
            }
        }
    }
}

// ============================================================================
// 512-thread smem-GEMM step: warp tile 32x32 (16 warps, 4 wm x 4 wn)
// ============================================================================
__device__ __forceinline__ void ff_gemm512(uint32_t sbase, uint32_t aHi, uint32_t aLo,
                                           uint32_t wHi, uint32_t wLo,
                                           int lane, int wm, int wn, float acc[2][4][4])
{
    const int a_row = (lane & 15);
    const int a_k   = (lane >> 4) << 3;
    const int b_row = (lane & 7) + ((lane >> 4) << 3);
    const int b_k   = ((lane >> 3) & 1) << 3;
    #pragma unroll
    for (int ks = 0; ks < 8; ks++) {
        const int ka = ks << 4;
        uint32_t bh[4][2], bl[4][2];
        #pragma unroll
        for (int np = 0; np < 2; np++) {
            uint32_t roff = ((uint32_t)(wn * 32 + np * 16 + b_row) * 136 + ka + b_k) * 2u;
            uint32_t rh[4], rl[4];
            ldsm_x4(sbase + wHi + roff, rh);
            ldsm_x4(sbase + wLo + roff, rl);
            bh[np*2][0] = rh[0]; bh[np*2][1] = rh[1];
            bh[np*2+1][0] = rh[2]; bh[np*2+1][1] = rh[3];
            bl[np*2][0] = rl[0]; bl[np*2][1] = rl[1];
            bl[np*2+1][0] = rl[2]; bl[np*2+1][1] = rl[3];
        }
        uint32_t ah[2][4], al[2][4];
        #pragma unroll
        for (int mt = 0; mt < 2; mt++) {
            uint32_t roff = ((uint32_t)(wm * 32 + mt * 16 + a_row) * 136 + ka + a_k) * 2u;
            ldsm_x4(sbase + aHi + roff, ah[mt]);
            ldsm_x4(sbase + aLo + roff, al[mt]);
        }
        #pragma unroll
        for (int mt = 0; mt < 2; mt++)
            #pragma unroll
            for (int nt = 0; nt < 4; nt++) {
                mma_bf16(acc[mt][nt], ah[mt], bh[nt]);
                mma_bf16(acc[mt][nt], ah[mt], bl[nt]);
                mma_bf16(acc[mt][nt], al[mt], bh[nt]);
            }
    }
}

// ============================================================================
// Merged fused FFN, 512 threads (4 warps/SMSP at 1 CTA/SM).
// out = bn1(x) + relu(bn1(x)@W1 + b1)@W2 + b2, BN2 stats fused.
// ============================================================================
#define FF_A_HI 0
#define FF_A_LO 34816
#define FF_H_HI 69632
#define FF_H_LO 104448
#define FF_W_HI 139264
#define FF_W_LO 174080

struct F2 {
    const float* A[2];
    const __nv_bfloat16 *W1hi[2], *W1lo[2], *W2hi[2], *W2lo[2];
    const float *b1[2], *b2[2];
    float* C[2];
    const float *Asc[2], *Ash[2];
    double *sumP[2], *sqP[2];
    int tileEnd0;
    int M[2];
};

__global__ __launch_bounds__(512, 1)
void k_ffn_multi(F2 p, int totTiles)
{
    extern __shared__ char smem[];
    const uint32_t sbase = smem_u32(smem);
    const int tid  = threadIdx.x;
    const int lane = tid & 31;
    const int wid  = tid >> 5;      // 0..15
    const int wm   = wid >> 2;      // 0..3
    const int wn   = wid & 3;       // 0..3
    const int g    = lane >> 2;
    const int t2   = (lane & 3) << 1;

    for (int t = blockIdx.x; t < totTiles; t += gridDim.x) {
        const int pr = (t >= p.tileEnd0) ? 1 : 0;
        const int tl = pr ? (t - p.tileEnd0) : t;
        const int m0 = tl << 7;
        const int M  = p.M[pr];
        const float* A   = p.A[pr];
        const float* Asc = p.Asc[pr];
        const float* Ash = p.Ash[pr];
        __syncthreads();

        // stage A = bn1(x): 128 rows x 32 float4 = 4096 over 512 threads
        #pragma unroll
        for (int j = 0; j < 8; j++) {
            int idx = tid + (j << 9);
            int row = idx >> 5;
            int c4  = (idx & 31) << 2;
            int gm = m0 + row; if (gm > M - 1) gm = M - 1;
            float4 v = *(const float4*)(A + (size_t)gm * 128 + c4);
            float4 sc = *(const float4*)(Asc + c4);
            float4 sh = *(const float4*)(Ash + c4);
            v.x = v.x * sc.x + sh.x;
            v.y = v.y * sc.y + sh.y;
            v.z = v.z * sc.z + sh.z;
            v.w = v.w * sc.w + sh.w;
            uint32_t h01, l01, h23, l23;
            split_pair(v.x, v.y, h01, l01);
            split_pair(v.z, v.w, h23, l23);
            uint32_t off = ((uint32_t)row * 136 + c4) * 2u;
            *(uint2*)(smem + FF_A_HI + off) = make_uint2(h01, h23);
            *(uint2*)(smem + FF_A_LO + off) = make_uint2(l01, l23);
        }
        {
            const __nv_bfloat16* W1hi = p.W1hi[pr];
            const __nv_bfloat16* W1lo = p.W1lo[pr];
            #pragma unroll
            for (int i0 = 0; i0 < 4; i0++) {
                int i = tid + (i0 << 9);
                int n = i >> 4, k8 = i & 15;
                uint4 vh = *(const uint4*)(W1hi + (size_t)n * 128 + (k8 << 3));
                uint4 vl = *(const uint4*)(W1lo + (size_t)n * 128 + (k8 << 3));
                uint32_t off = ((uint32_t)n * 136 + (k8 << 3)) * 2u;
                *(uint4*)(smem + FF_W_HI + off) = vh;
                *(uint4*)(smem + FF_W_LO + off) = vl;
            }
        }
        __syncthreads();

        float acc2[2][4][4] = {};
        #pragma unroll
        for (int nh = 0; nh < 2; nh++) {
            float acc1[2][4][4] = {};
            ff_gemm512(sbase, FF_A_HI, FF_A_LO, FF_W_HI, FF_W_LO, lane, wm, wn, acc1);
            __syncthreads();
            #pragma unroll
            for (int mt = 0; mt < 2; mt++) {
                #pragma unroll
                for (int nt = 0; nt < 4; nt++) {
                    int c = wn * 32 + nt * 8 + t2;
                    float2 bv = *(const float2*)(p.b1[pr] + nh * 128 + c);
                    #pragma unroll
                    for (int half = 0; half < 2; half++) {
                        int rloc = wm * 32 + mt * 16 + g + half * 8;
                        float v0 = fmaxf(acc1[mt][nt][half*2]   + bv.x, 0.f);
                        float v1 = fmaxf(acc1[mt][nt][half*2+1] + bv.y, 0.f);
                        uint32_t hi, lo;
                        split_pair(v0, v1, hi, lo);
                        uint32_t off = ((uint32_t)rloc * 136 + c) * 2u;
                        *(uint32_t*)(smem + FF_H_HI + off) = hi;
                        *(uint32_t*)(smem + FF_H_LO + off) = lo;
                    }
                }
            }
            {
                const __nv_bfloat16* W2hi = p.W2hi[pr];
                const __nv_bfloat16* W2lo = p.W2lo[pr];
                #pragma unroll
                for (int i0 = 0; i0 < 4; i0++) {
                    int i = tid + (i0 << 9);
                    int n = i >> 4, k8 = i & 15;
                    uint4 vh = *(const uint4*)(W2hi + (size_t)n * 256 + nh * 128 + (k8 << 3));
                    uint4 vl = *(const uint4*)(W2lo + (size_t)n * 256 + nh * 128 + (k8 << 3));
                    uint32_t off = ((uint32_t)n * 136 + (k8 << 3)) * 2u;
                    *(uint4*)(smem + FF_W_HI + off) = vh;
                    *(uint4*)(smem + FF_W_LO + off) = vl;
                }
            }
            __syncthreads();
            ff_gemm512(sbase, FF_H_HI, FF_H_LO, FF_W_HI, FF_W_LO, lane, wm, wn, acc2);
            if (nh == 0) {
                __syncthreads();
                const __nv_bfloat16* W1hi = p.W1hi[pr];
                const __nv_bfloat16* W1lo = p.W1lo[pr];
                #pragma unroll
                for (int i0 = 0; i0 < 4; i0++) {
                    int i = tid + (i0 << 9);
                    int n = i >> 4, k8 = i & 15;
                    uint4 vh = *(const uint4*)(W1hi + (size_t)(128 + n) * 128 + (k8 << 3));
                    uint4 vl = *(const uint4*)(W1lo + (size_t)(128 + n) * 128 + (k8 << 3));
                    uint32_t off = ((uint32_t)n * 136 + (k8 << 3)) * 2u;
                    *(uint4*)(smem + FF_W_HI + off) = vh;
                    *(uint4*)(smem + FF_W_LO + off) = vl;
                }
                __syncthreads();
            }
        }

        float* C = p.C[pr];
        #pragma unroll
        for (int nt = 0; nt < 4; nt++) {
            int c0 = wn * 32 + nt * 8 + t2;
            float2 bv = *(const float2*)(p.b2[pr] + c0);
            float ps0 = 0.f, ps1 = 0.f, q0 = 0.f, q1 = 0.f;
            #pragma unroll
            for (int mt = 0; mt < 2; mt++) {
                #pragma unroll
                for (int half = 0; half < 2; half++) {
                    int rloc = wm * 32 + mt * 16 + g + half * 8;
                    int r = m0 + rloc;
                    uint32_t off = ((uint32_t)rloc * 136 + c0) * 2u;
                    __nv_bfloat162 rh = *(__nv_bfloat162*)(smem + FF_A_HI + off);
                    __nv_bfloat162 rl = *(__nv_bfloat162*)(smem + FF_A_LO + off);
                    float2 v;
                    v.x = acc2[mt][nt][half*2]   + bv.x
                        + __bfloat162float(__low2bfloat16(rh))
                        + __bfloat162float(__low2bfloat16(rl));
                    v.y = acc2[mt][nt][half*2+1] + bv.y
                        + __bfloat162float(__high2bfloat16(rh))
                        + __bfloat162float(__high2bfloat16(rl));
                    if (r < M) {
                        *(float2*)(C + (size_t)r * 128 + c0) = v;
                    } else { v.x = 0.f; v.y = 0.f; }
                    ps0 += v.x; q0 += v.x * v.x;
                    ps1 += v.y; q1 += v.y * v.y;
                }
            }
            #pragma unroll
            for (int off = 16; off >= 4; off >>= 1) {
                ps0 += __shfl_down_sync(0xffffffffu, ps0, off);
                ps1 += __shfl_down_sync(0xffffffffu, ps1, off);
                q0  += __shfl_down_sync(0xffffffffu, q0,  off);
                q1  += __shfl_down_sync(0xffffffffu, q1,  off);
            }
            if (lane < 4) {
                int cc = wn * 32 + nt * 8 + lane * 2;
                atomicAdd(&p.sumP[pr][cc],     (double)ps0);
                atomicAdd(&p.sumP[pr][cc + 1], (double)ps1);
                atomicAdd(&p.sqP[pr][cc],      (double)q0);
                atomicAdd(&p.sqP[pr][cc + 1],  (double)q1);
            }
        }
    }
}

// ---------------- edge kernel: 1 warp = 4 edges, float4 vector atomics ------
__global__ __launch_bounds__(256)
void k_edge(const int* __restrict__ src, const int* __restrict__ dst)
{
    const int lane = threadIdx.x & 31;
    const int e0 = (blockIdx.x * 8 + (threadIdx.x >> 5)) * 4;
    const int c4 = lane << 2;
    int s[4], d[4];
    #pragma unroll
    for (int i = 0; i < 4; i++) { s[i] = src[e0 + i]; d[i] = dst[e0 + i]; }
    float4 kv[4], qv[4], ev[4], vv[4];
    #pragma unroll
    for (int i = 0; i < 4; i++) {
        kv[i] = *(const float4*)(g_K + (size_t)s[i] * 128 + c4);
        qv[i] = *(const float4*)(g_Q + (size_t)d[i] * 128 + c4);
        ev[i] = *(const float4*)(g_EA + (size_t)(e0 + i) * 128 + c4);
        vv[i] = *(const float4*)(g_V + (size_t)s[i] * 128 + c4);
    }
    #pragma unroll
    for (int i = 0; i < 4; i++) {
        float4 sc;
        sc.x = kv[i].x * qv[i].x * 0.25f * ev[i].x;
        sc.y = kv[i].y * qv[i].y * 0.25f * ev[i].y;
        sc.z = kv[i].z * qv[i].z * 0.25f * ev[i].z;
        sc.w = kv[i].w * qv[i].w * 0.25f * ev[i].w;
        *(float4*)(g_EA + (size_t)(e0 + i) * 128 + c4) = sc;
        float sum = sc.x + sc.y + sc.z + sc.w;
        sum += __shfl_xor_sync(0xffffffffu, sum, 1);
        sum += __shfl_xor_sync(0xffffffffu, sum, 2);
        sum = fminf(fmaxf(sum, -5.f), 5.f);
        float ss = __expf(sum);
        float4 add = make_float4(vv[i].x * ss, vv[i].y * ss, vv[i].z * ss, vv[i].w * ss);
        atomicAdd((float4*)(g_wV + (size_t)d[i] * 128 + c4), add);
        if ((lane & 3) == 0)
            atomicAdd(&g_z[(size_t)d[i] * 8 + (lane >> 2)], ss);
    }
}

// ---------------- batch-norm finalize (2 slots) / merged apply --------------
__global__ void k_bn_fin2(int slotA, float MfA, const float* gA, const float* bA,
                          int slotB, float MfB, const float* gB, const float* bB)
{
    int c = threadIdx.x & 127;
    int slot; float Mf; const float *gg, *bb;
    if (threadIdx.x < 128) { slot = slotA; Mf = MfA; gg = gA; bb = bA; }
    else                   { slot = slotB; Mf = MfB; gg = gB; bb = bB; }
    double mu  = g_sum[slot * 128 + c] / (double)Mf;
    double var = g_sq [slot * 128 + c] / (double)Mf - mu * mu;
    float sc = gg[c] * rsqrtf((float)var + 1e-5f);
    g_bnsc[slot * 128 + c] = sc;
    g_bnsh[slot * 128 + c] = bb[c] - (float)mu * sc;
}

__global__ __launch_bounds__(256)
void k_bn_apply2(float* __restrict__ Xh, float* __restrict__ Xe)
{
    const size_t totH = (size_t)NN * 32;
    const size_t tot  = totH + (size_t)EG * 32;
    size_t i = (size_t)blockIdx.x * blockDim.x + threadIdx.x;
    size_t stride = (size_t)gridDim.x * blockDim.x;
    for (size_t j = i; j < tot; j += stride) {
        bool isH = j < totH;
        float* X = isH ? Xh : Xe;
        size_t jj = isH ? j : j - totH;
        int slot = isH ? 2 : 3;
        int c = (int)(jj & 31) * 4;
        const float* sc = g_bnsc + slot * 128 + c;
        const float* sh = g_bnsh + slot * 128 + c;
        float4 v = ((float4*)X)[jj];
        v.x = v.x * sc[0] + sh[0];
        v.y = v.y * sc[1] + sh[1];
        v.z = v.z * sc[2] + sh[2];
        v.w = v.w * sc[3] + sh[3];
        ((float4*)X)[jj] = v;
    }
}

// ---------------- host orchestration ---------------------------------------
extern "C" void kernel_launch(void* const* d_in, const int* in_sizes, int n_in,
                              void* d_out, int out_size)
{
    const float* h   = (const float*)d_in[0];
    const float* e   = (const float*)d_in[1];
    const int*   src = (const int*)d_in[2];
    const int*   dst = (const int*)d_in[3];
    const float* WQ  = (const float*)d_in[4];   const float* bQ  = (const float*)d_in[5];
    const float* WK  = (const float*)d_in[6];   const float* bK  = (const float*)d_in[7];
    const float* WV  = (const float*)d_in[8];   const float* bV  = (const float*)d_in[9];
    const float* WE  = (const float*)d_in[10];  const float* bE  = (const float*)d_in[11];
    const float* WOh = (const float*)d_in[12];  const float* bOh = (const float*)d_in[13];
    const float* WOe = (const float*)d_in[14];  const float* bOe = (const float*)d_in[15];
    const float* Wh1 = (const float*)d_in[16];  const float* bh1 = (const float*)d_in[17];
    const float* Wh2 = (const float*)d_in[18];  const float* bh2 = (const float*)d_in[19];
    const float* We1 = (const float*)d_in[20];  const float* be1 = (const float*)d_in[21];
    const float* We2 = (const float*)d_in[22];  const float* be2 = (const float*)d_in[23];
    const float* g1h = (const float*)d_in[24];
    const float* g1e = (const float*)d_in[25];
    const float* g2h = (const float*)d_in[26];
    const float* g2e = (const float*)d_in[27];
    const float* b1h = (const float*)d_in[28];
    const float* b1e = (const float*)d_in[29];
    const float* b2h = (const float*)d_in[30];
    const float* b2e = (const float*)d_in[31];

    float *pQ, *pK, *pV, *ph1, *pEA, *pe1, *pbnsc, *pbnsh, *pwV, *pz;
    double *psum, *psq;
    __nv_bfloat16* wb;
    cudaGetSymbolAddress((void**)&pQ,    g_Q);
    cudaGetSymbolAddress((void**)&pK,    g_K);
    cudaGetSymbolAddress((void**)&pV,    g_V);
    cudaGetSymbolAddress((void**)&ph1,   g_h1);
    cudaGetSymbolAddress((void**)&pEA,   g_EA);
    cudaGetSymbolAddress((void**)&pe1,   g_e1);
    cudaGetSymbolAddress((void**)&pbnsc, g_bnsc);
    cudaGetSymbolAddress((void**)&pbnsh, g_bnsh);
    cudaGetSymbolAddress((void**)&pwV,   g_wV);
    cudaGetSymbolAddress((void**)&pz,    g_z);
    cudaGetSymbolAddress((void**)&psum,  g_sum);
    cudaGetSymbolAddress((void**)&psq,   g_sq);
    cudaGetSymbolAddress((void**)&wb,    g_Wb);

    cudaFuncSetAttribute(k_gemm_multi, cudaFuncAttributeMaxDynamicSharedMemorySize, 110592);
    cudaFuncSetAttribute(k_ffn_multi,  cudaFuncAttributeMaxDynamicSharedMemorySize, 208896);

    float* out_h = (float*)d_out;
    float* out_e = (float*)d_out + (size_t)NN * 128;

    const int tilesH = (NN + 127) / 128;   // 391
    const int tilesE = (EG + 127) / 128;   // 6250

    // 0) zero + weight pre-split
    k_zero<<<4096, 256>>>();
    k_wsplit<<<448, 256>>>(WQ, WK, WV, WE, WOh, WOe, Wh1, We1, Wh2, We2);

    // 1) all four projections in one launch: Q, K, V (A=h), E (A=e)
    {
        P4 p = {};
        p.nprob = 4;
        p.A[0] = h;  p.A[1] = h;  p.A[2] = h;  p.A[3] = e;
        p.Whi[0] = wb + OFF_WQ; p.Wlo[0] = wb + OFF_WQ + TOTW;
        p.Whi[1] = wb + OFF_WK; p.Wlo[1] = wb + OFF_WK + TOTW;
        p.Whi[2] = wb + OFF_WV; p.Wlo[2] = wb + OFF_WV + TOTW;
        p.Whi[3] = wb + OFF_WE; p.Wlo[3] = wb + OFF_WE + TOTW;
        p.bias[0] = bQ; p.bias[1] = bK; p.bias[2] = bV; p.bias[3] = bE;
        p.C[0] = pQ; p.C[1] = pK; p.C[2] = pV; p.C[3] = pEA;
        p.M[0] = NN; p.M[1] = NN; p.M[2] = NN; p.M[3] = EG;
        p.tileEnd[0] = tilesH;
        p.tileEnd[1] = tilesH * 2;
        p.tileEnd[2] = tilesH * 3;
        p.tileEnd[3] = tilesH * 3 + tilesE;
        int tot = p.tileEnd[3];
        int grid = tot < 296 ? tot : 296;
        k_gemm_multi<<<grid, 256, 110592>>>(p, tot);
    }

    // 2) edge scores + attention weights + segment sums
    k_edge<<<EG / 32, 256>>>(src, dst);

    // 3) O projections (Oh with Zrow + BN1h stats, Oe + BN1e stats) merged
    {
        P4 p = {};
        p.nprob = 2;
        p.A[0] = pwV; p.A[1] = pEA;
        p.Whi[0] = wb + OFF_WOH; p.Wlo[0] = wb + OFF_WOH + TOTW;
        p.Whi[1] = wb + OFF_WOE; p.Wlo[1] = wb + OFF_WOE + TOTW;
        p.bias[0] = bOh; p.bias[1] = bOe;
        p.res[0] = h;  p.res[1] = e;
        p.C[0] = ph1;  p.C[1] = pe1;
        p.Zrow[0] = pz;
        p.sumP[0] = psum + 0;   p.sqP[0] = psq + 0;
        p.sumP[1] = psum + 128; p.sqP[1] = psq + 128;
        p.M[0] = NN; p.M[1] = EG;
        p.tileEnd[0] = tilesH;
        p.tileEnd[1] = tilesH + tilesE;
        int tot = p.tileEnd[1];
        int grid = tot < 296 ? tot : 296;
        k_gemm_multi<<<grid, 256, 110592>>>(p, tot);
    }

    // 4) BN #1 finalize (both slots, one launch)
    k_bn_fin2<<<1, 256>>>(0, (float)NN, g1h, b1h, 1, (float)EG, g1e, b1e);

    // 5) fused FFNs, h + e merged, 512 threads
    {
        F2 p = {};
        p.A[0] = ph1; p.A[1] = pe1;
        p.W1hi[0] = wb + OFF_WH1; p.W1lo[0] = wb + OFF_WH1 + TOTW;
        p.W1hi[1] = wb + OFF_WE1; p.W1lo[1] = wb + OFF_WE1 + TOTW;
        p.W2hi[0] = wb + OFF_WH2; p.W2lo[0] = wb + OFF_WH2 + TOTW;
        p.W2hi[1] = wb + OFF_WE2; p.W2lo[1] = wb + OFF_WE2 + TOTW;
        p.b1[0] = bh1; p.b1[1] = be1;
        p.b2[0] = bh2; p.b2[1] = be2;
        p.C[0] = out_h; p.C[1] = out_e;
        p.Asc[0] = pbnsc + 0;   p.Ash[0] = pbnsh + 0;
        p.Asc[1] = pbnsc + 128; p.Ash[1] = pbnsh + 128;
        p.sumP[0] = psum + 256; p.sqP[0] = psq + 256;
        p.sumP[1] = psum + 384; p.sqP[1] = psq + 384;
        p.tileEnd0 = tilesH;
        p.M[0] = NN; p.M[1] = EG;
        int tot = tilesH + tilesE;
        int grid = tot < 148 ? tot : 148;
        k_ffn_multi<<<grid, 512, 208896>>>(p, tot);
    }

    // 6) BN #2 finalize + merged apply
    k_bn_fin2<<<1, 256>>>(2, (float)NN, g2h, b2h, 3, (float)EG, g2e, b2e);
    k_bn_apply2<<<8192, 256>>>(out_h, out_e);
}